// round 1
// baseline (speedup 1.0000x reference)
#include <cuda_runtime.h>
#include <cuda_bf16.h>
#include <math_constants.h>

#define SEG_B 16384

// Per-segment packed state: low 32 bits = max (f32 bits), high 32 bits = sum (f32 bits)
__device__ unsigned long long g_seg_ms[SEG_B];
// Finalized per-segment table: {max, 1/sum}
__device__ float2 g_seg_tab[SEG_B];

__device__ __forceinline__ void merge_global(unsigned long long* addr, float m, float s) {
    unsigned long long cur = *addr;
    for (;;) {
        float cm = __uint_as_float((unsigned int)(cur & 0xffffffffULL));
        float cs = __uint_as_float((unsigned int)(cur >> 32));
        float nm = fmaxf(cm, m);
        // cm may be -inf (init): __expf(-inf) == 0, so cs term vanishes correctly.
        float ns = cs * __expf(cm - nm) + s * __expf(m - nm);
        unsigned long long nv =
            ((unsigned long long)__float_as_uint(ns) << 32) |
            (unsigned long long)__float_as_uint(nm);
        unsigned long long prev = atomicCAS(addr, cur, nv);
        if (prev == cur) return;
        cur = prev;
    }
}

__global__ void __launch_bounds__(256) k_init() {
    int i = blockIdx.x * 256 + threadIdx.x;
    if (i < SEG_B) {
        // max = -inf, sum = 0
        g_seg_ms[i] = (unsigned long long)__float_as_uint(-CUDART_INF_F);
    }
}

// Pass 1: fused (max, sum-of-exp) segmented reduction.
// Each thread: 8 contiguous elements (2x float4/int4). Warp: 256 contiguous.
__global__ void __launch_bounds__(256) k_pass1(const float* __restrict__ x,
                                               const int* __restrict__ ids,
                                               int n) {
    int t = blockIdx.x * 256 + threadIdx.x;
    int base = t * 8;

    float xs[8];
    int ss[8];

    if (base + 8 <= n) {
        float4 a = __ldcs(reinterpret_cast<const float4*>(x + base));
        float4 b = __ldcs(reinterpret_cast<const float4*>(x + base) + 1);
        int4 ia = __ldcs(reinterpret_cast<const int4*>(ids + base));
        int4 ib = __ldcs(reinterpret_cast<const int4*>(ids + base) + 1);
        xs[0] = a.x; xs[1] = a.y; xs[2] = a.z; xs[3] = a.w;
        xs[4] = b.x; xs[5] = b.y; xs[6] = b.z; xs[7] = b.w;
        ss[0] = ia.x; ss[1] = ia.y; ss[2] = ia.z; ss[3] = ia.w;
        ss[4] = ib.x; ss[5] = ib.y; ss[6] = ib.z; ss[7] = ib.w;
    } else {
#pragma unroll
        for (int j = 0; j < 8; j++) {
            int idx = base + j;
            if (idx < n) { xs[j] = x[idx]; ss[j] = ids[idx]; }
            else         { xs[j] = 0.0f;   ss[j] = -1; }       // sentinel run, skipped
        }
    }

    // Within-thread run reduction (online softmax per run).
    int   head_seg = -1;
    float head_m = 0.0f, head_s = 0.0f;
    int   cur_seg = ss[0];
    float cur_m   = xs[0];
    float cur_s   = 1.0f;
    bool  have_head = false;

#pragma unroll
    for (int j = 1; j < 8; j++) {
        if (ss[j] == cur_seg) {
            float xv = xs[j];
            if (xv > cur_m) {
                cur_s = cur_s * __expf(cur_m - xv) + 1.0f;
                cur_m = xv;
            } else {
                cur_s += __expf(xv - cur_m);
            }
        } else {
            if (!have_head) {
                head_seg = cur_seg; head_m = cur_m; head_s = cur_s; have_head = true;
            } else if (cur_seg >= 0) {
                merge_global(g_seg_ms + cur_seg, cur_m, cur_s);   // rare path
            }
            cur_seg = ss[j]; cur_m = xs[j]; cur_s = 1.0f;
        }
    }
    if (!have_head) {
        head_seg = cur_seg; head_m = cur_m; head_s = cur_s;
    } else if (cur_seg >= 0) {
        merge_global(g_seg_ms + cur_seg, cur_m, cur_s);           // rare path
    }

    // Warp-level segmented reduction on head partials.
    // Head segs are monotone non-decreasing across lanes; merging is associative
    // and commutative, so any grouping into g_seg_ms is correct.
    const unsigned mask = 0xffffffffu;
    int lane = threadIdx.x & 31;
    int   seg = head_seg;
    float m   = head_m;
    float s   = head_s;
#pragma unroll
    for (int d = 1; d < 32; d <<= 1) {
        int   seg_o = __shfl_down_sync(mask, seg, d);
        float m_o   = __shfl_down_sync(mask, m, d);
        float s_o   = __shfl_down_sync(mask, s, d);
        if (lane + d < 32 && seg_o == seg) {
            float nm = fmaxf(m, m_o);
            s = s * __expf(m - nm) + s_o * __expf(m_o - nm);
            m = nm;
        }
    }
    int seg_prev = __shfl_up_sync(mask, seg, 1);
    if ((lane == 0 || seg_prev != seg) && seg >= 0) {
        merge_global(g_seg_ms + seg, m, s);
    }
}

__global__ void __launch_bounds__(256) k_finalize() {
    int i = blockIdx.x * 256 + threadIdx.x;
    if (i < SEG_B) {
        unsigned long long v = g_seg_ms[i];
        float m = __uint_as_float((unsigned int)(v & 0xffffffffULL));
        float s = __uint_as_float((unsigned int)(v >> 32));
        g_seg_tab[i] = make_float2(m, 1.0f / s);
    }
}

// Pass 2: out[i] = exp(x[i] - max[seg]) * (1/sum[seg])
__global__ void __launch_bounds__(256) k_pass2(const float* __restrict__ x,
                                               const int* __restrict__ ids,
                                               float* __restrict__ out,
                                               int n) {
    int t = blockIdx.x * 256 + threadIdx.x;
    int base = t * 4;
    if (base + 4 <= n) {
        float4 xv = __ldcs(reinterpret_cast<const float4*>(x + base));
        int4  iv  = __ldcs(reinterpret_cast<const int4*>(ids + base));
        float2 ta = g_seg_tab[iv.x];
        float2 tb = g_seg_tab[iv.y];
        float2 tc = g_seg_tab[iv.z];
        float2 td = g_seg_tab[iv.w];
        float4 o;
        o.x = __expf(xv.x - ta.x) * ta.y;
        o.y = __expf(xv.y - tb.x) * tb.y;
        o.z = __expf(xv.z - tc.x) * tc.y;
        o.w = __expf(xv.w - td.x) * td.y;
        __stcs(reinterpret_cast<float4*>(out + base), o);
    } else {
        for (int idx = base; idx < n; idx++) {
            float2 tv = g_seg_tab[ids[idx]];
            out[idx] = __expf(x[idx] - tv.x) * tv.y;
        }
    }
}

extern "C" void kernel_launch(void* const* d_in, const int* in_sizes, int n_in,
                              void* d_out, int out_size) {
    const float* x   = (const float*)d_in[0];
    const int*   ids = (const int*)d_in[1];
    float*       out = (float*)d_out;
    int n = in_sizes[0];

    k_init<<<(SEG_B + 255) / 256, 256>>>();

    int t1 = (n + 7) / 8;
    k_pass1<<<(t1 + 255) / 256, 256>>>(x, ids, n);

    k_finalize<<<(SEG_B + 255) / 256, 256>>>();

    int t2 = (n + 3) / 4;
    k_pass2<<<(t2 + 255) / 256, 256>>>(x, ids, out, n);
}